// round 3
// baseline (speedup 1.0000x reference)
#include <cuda_runtime.h>
#include <cstdint>

// ---------------- static scratch ----------------
__device__ uint8_t g_bins[6 * 514 * 520];          // quantized bins, zero-padded (pad=1), col stride 520
__device__ uint8_t g_mode[6 * 504 * 512];          // mode-pool result (bin index), col stride 512
__device__ float   g_d1[128 * 168 * 168];
__device__ float   g_d2[128 * 56 * 56];
__device__ float   g_d3[128 * 19 * 19];
__device__ float   g_d4[128 * 7 * 7];
__device__ float   g_d5[128 * 3 * 3];
__device__ float   g_score[(size_t)128 * 512 * 512];

__device__ __forceinline__ float leaky_(float v) { return v >= 0.f ? v : 0.01f * v; }
__device__ __forceinline__ float max_leaky_(float v) { return v <= 0.1f ? v : fmaf(0.01f, v - 0.1f, 0.1f); }
__device__ __forceinline__ float min_leaky_(float v) { return v >= 0.1f ? v : fmaf(0.01f, v - 0.1f, 0.1f); }

// ---------------- K0: quantize to bins (zero padded layout) ----------------
__global__ void k_bins(const float* __restrict__ x) {
    int total = 6 * 514 * 520;
    for (int idx = blockIdx.x * blockDim.x + threadIdx.x; idx < total;
         idx += gridDim.x * blockDim.x) {
        int c = idx % 520;
        int t = idx / 520;
        int r = t % 514;
        int p = t / 514;
        uint8_t v = 0;
        if (c >= 1 && c <= 512 && r >= 1 && r <= 512) {
            float xv = x[((size_t)p * 512 + (r - 1)) * 512 + (c - 1)];
            float q = rintf((xv * 255.0f) * 0.0625f);   // matches jnp.round(x*255/16), half-even
            q = fminf(fmaxf(q, 0.0f), 16.0f);
            v = (uint8_t)q;
        }
        g_bins[idx] = v;
    }
}

// ---------------- K1: mode pool 11x11 stride 1 (smem sliding histogram) ----------------
// thread task: one (plane,row,28-col chunk); hist[b] at smem [b*128 + tid] -> conflict free
__global__ __launch_bounds__(128) void k_mode() {
    __shared__ uint32_t hist[17 * 128];
    int t = threadIdx.x;
    int task = blockIdx.x * 128 + t;
    if (task >= 6 * 504 * 18) return;
    uint32_t* h = hist + t;
#pragma unroll
    for (int b = 0; b < 17; b++) h[b * 128] = 0;

    int chunk = task % 18;
    int row = (task / 18) % 504;
    int p = task / (18 * 504);
    int c0 = chunk * 28;
    const uint8_t* base = g_bins + ((size_t)p * 514 + row) * 520;
    for (int r = 0; r < 11; r++) {
        const uint8_t* rp = base + r * 520 + c0;
#pragma unroll
        for (int c = 0; c < 11; c++) h[(int)rp[c] * 128]++;
    }
    uint8_t* outp = g_mode + ((size_t)p * 504 + row) * 512;
    int s = 0;
    for (;;) {
        int best = -1, bi = 0;
#pragma unroll
        for (int b = 0; b < 17; b++) {
            int v = (int)h[b * 128];
            if (v > best) { best = v; bi = b; }
        }
        outp[c0 + s] = (uint8_t)bi;
        if (++s == 28) break;
        int addc = c0 + s + 10, remc = c0 + s - 1;
        for (int r = 0; r < 11; r++) {
            const uint8_t* rp = base + r * 520;
            h[(int)rp[addc] * 128]++;
            h[(int)rp[remc] * 128]--;
        }
    }
}

// ---------------- K2: fused mode -> 1x1 -> maxleaky -> grouped 1x1 -> minleaky
//                      -> shared 3x3 stride-3 conv -> leaky ==> d1 [2,64,168,168]
__global__ __launch_bounds__(256) void k_d1(
    const float* __restrict__ w1, const float* __restrict__ b1,
    const float* __restrict__ w2, const float* __restrict__ b2,
    const float* __restrict__ dk, const float* __restrict__ db) {
    __shared__ uint8_t ms[3][24][96];
    __shared__ float pw[448];
    __shared__ float kk[9];
    __shared__ float bias;
    int b = blockIdx.z;
    int y0 = blockIdx.y * 8, x0 = blockIdx.x * 32;
    int tid = threadIdx.y * 32 + threadIdx.x;
    for (int i = tid; i < 448; i += 256) {
        float v;
        if (i < 192) v = w1[i];
        else if (i < 256) v = b1[i - 192];
        else if (i < 384) v = w2[i - 256];
        else v = b2[i - 384];
        pw[i] = v;
    }
    if (tid < 9) kk[tid] = dk[tid];
    if (tid == 0) bias = db[0];
    for (int i = tid; i < 3 * 24 * 96; i += 256) {
        int cc = i % 96;
        int tt = i / 96;
        int rr = tt % 24;
        int ch = tt / 24;
        int gr = 3 * y0 - 1 + rr, gc = 3 * x0 - 1 + cc;
        uint8_t v = 0;
        if (gr >= 0 && gr < 504 && gc >= 0 && gc < 504)
            v = g_mode[((size_t)(b * 3 + ch) * 504 + gr) * 512 + gc];
        ms[ch][rr][cc] = v;
    }
    __syncthreads();
    int x = x0 + threadIdx.x, y = y0 + threadIdx.y;
    if (x >= 168) return;     // y < 168 always (21*8)

    float m0[9], m1[9], m2[9];
    bool ok[9];
#pragma unroll
    for (int r = 0; r < 3; r++)
#pragma unroll
        for (int cc = 0; cc < 3; cc++) {
            int pos = r * 3 + cc;
            int gr = 3 * y - 1 + r, gc = 3 * x - 1 + cc;
            ok[pos] = (gr >= 0 && gr < 504 && gc >= 0 && gc < 504);
            int lr = 3 * (int)threadIdx.y + r, lc = 3 * (int)threadIdx.x + cc;
            m0[pos] = (float)ms[0][lr][lc] * (1.0f / 16.0f);
            m1[pos] = (float)ms[1][lr][lc] * (1.0f / 16.0f);
            m2[pos] = (float)ms[2][lr][lc] * (1.0f / 16.0f);
        }
    const float* W1 = pw;
    const float* B1 = pw + 192;
    const float* W2 = pw + 256;
    const float* B2 = pw + 384;
    float* o = g_d1 + (size_t)b * 64 * 168 * 168;
    for (int g = 0; g < 32; g++) {
        int ca = 2 * g, cb = ca + 1;
        float wa0 = W1[ca * 3], wa1 = W1[ca * 3 + 1], wa2 = W1[ca * 3 + 2], ba = B1[ca];
        float wb0 = W1[cb * 3], wb1 = W1[cb * 3 + 1], wb2 = W1[cb * 3 + 2], bb = B1[cb];
        float u00 = W2[ca * 2], u01 = W2[ca * 2 + 1], c0b = B2[ca];
        float u10 = W2[cb * 2], u11 = W2[cb * 2 + 1], c1b = B2[cb];
        float acc0 = 0.f, acc1 = 0.f;
#pragma unroll
        for (int pos = 0; pos < 9; pos++) {
            if (!ok[pos]) continue;
            float ha = max_leaky_(fmaf(wa2, m2[pos], fmaf(wa1, m1[pos], fmaf(wa0, m0[pos], ba))));
            float hb = max_leaky_(fmaf(wb2, m2[pos], fmaf(wb1, m1[pos], fmaf(wb0, m0[pos], bb))));
            float v0 = min_leaky_(fmaf(u01, hb, fmaf(u00, ha, c0b)));
            float v1 = min_leaky_(fmaf(u11, hb, fmaf(u10, ha, c1b)));
            acc0 = fmaf(kk[pos], v0, acc0);
            acc1 = fmaf(kk[pos], v1, acc1);
        }
        o[((size_t)ca * 168 + y) * 168 + x] = leaky_(acc0 + bias);
        o[((size_t)cb * 168 + y) * 168 + x] = leaky_(acc1 + bias);
    }
}

// ---------------- level table ----------------
__device__ __forceinline__ const float* lvl_ptr(int l) {
    switch (l) {
        case 0: return g_d1;
        case 1: return g_d2;
        case 2: return g_d3;
        case 3: return g_d4;
        default: return g_d5;
    }
}
__device__ __forceinline__ int lvl_size(int l) {
    switch (l) {
        case 0: return 168;
        case 1: return 56;
        case 2: return 19;
        case 3: return 7;
        default: return 3;
    }
}

// ---------------- K3: generic downgrade (3x3 stride-3 pad-1 shared conv + leaky) ----------------
__global__ void k_down(int l, const float* __restrict__ dk, const float* __restrict__ db) {
    int Si = lvl_size(l - 1), So = lvl_size(l);
    const float* in = lvl_ptr(l - 1);
    float* out = (float*)lvl_ptr(l);
    int idx = blockIdx.x * blockDim.x + threadIdx.x;
    int total = 128 * So * So;
    if (idx >= total) return;
    int x = idx % So;
    int t = idx / So;
    int y = t % So;
    int p = t / So;
    const float* ip = in + (size_t)p * Si * Si;
    float acc = db[0];
#pragma unroll
    for (int r = 0; r < 3; r++) {
        int gy = 3 * y - 1 + r;
        if (gy < 0 || gy >= Si) continue;
#pragma unroll
        for (int cc = 0; cc < 3; cc++) {
            int gx = 3 * x - 1 + cc;
            if (gx < 0 || gx >= Si) continue;
            acc = fmaf(dk[r * 3 + cc], ip[gy * Si + gx], acc);
        }
    }
    out[idx] = leaky_(acc);
}

// ---------------- K4: fused 5x (bilinear resize -> 5x5 shared conv -> BN -> leaky -> accumulate)
// tile 64x64 per (plane); block 256 threads, 4x4 px/thread
#define ZST 76
__global__ __launch_bounds__(256) void k_interp(
    const float* __restrict__ interp_k, const float* __restrict__ interp_b,
    const float* __restrict__ i_gamma, const float* __restrict__ i_beta,
    const float* __restrict__ i_mean, const float* __restrict__ i_var) {
    __shared__ float zs[68 * ZST];
    __shared__ float ds[26 * 26];
    __shared__ float kk[25];
    __shared__ int jxs[68], jys[68];
    __shared__ float fxs[68], fys[68];

    int plane = blockIdx.z;
    int c = plane & 63;
    int tx0 = blockIdx.x * 64, ty0 = blockIdx.y * 64;
    int tid = threadIdx.x;
    int ttx = tid & 15, tty = tid >> 4;

    if (tid < 25) kk[tid] = interp_k[tid];
    float A, Bc;
    {
        float sc = i_gamma[c] * rsqrtf(i_var[c] + 1e-5f);
        A = sc;
        Bc = (interp_b[0] - i_mean[c]) * sc + i_beta[c];
    }
    float sacc[16];
#pragma unroll
    for (int i = 0; i < 16; i++) sacc[i] = 0.f;

    for (int l = 0; l < 5; l++) {
        int S = lvl_size(l);
        const float* dp = lvl_ptr(l) + (size_t)plane * S * S;
        float scale = (float)S * (1.0f / 512.0f);
        // coarse origins (closed form, identical on all threads)
        int c0x, c0y;
        {
            float in = fminf(fmaxf(((float)max(tx0 - 2, 0) + 0.5f) * scale - 0.5f, 0.f), (float)(S - 1));
            c0x = min((int)in, S - 2);
            in = fminf(fmaxf(((float)max(ty0 - 2, 0) + 0.5f) * scale - 0.5f, 0.f), (float)(S - 1));
            c0y = min((int)in, S - 2);
        }
        if (tid < 68) {
            int gx = tx0 - 2 + tid;
            int jx = -1;
            float fx = 0.f;
            if (gx >= 0 && gx < 512) {
                float in = fminf(fmaxf(((float)gx + 0.5f) * scale - 0.5f, 0.f), (float)(S - 1));
                int j0 = min((int)in, S - 2);
                fx = in - (float)j0;
                jx = j0 - c0x;
            }
            jxs[tid] = jx;
            fxs[tid] = fx;
            int gy = ty0 - 2 + tid;
            int jy = -1;
            float fy = 0.f;
            if (gy >= 0 && gy < 512) {
                float in = fminf(fmaxf(((float)gy + 0.5f) * scale - 0.5f, 0.f), (float)(S - 1));
                int j0 = min((int)in, S - 2);
                fy = in - (float)j0;
                jy = j0 - c0y;
            }
            jys[tid] = jy;
            fys[tid] = fy;
        }
        // load coarse tile (clamped)
        for (int i = tid; i < 26 * 26; i += 256) {
            int rr = i / 26, cc2 = i % 26;
            int ry = min(c0y + rr, S - 1);
            int rx = min(c0x + cc2, S - 1);
            ds[i] = dp[ry * S + rx];
        }
        __syncthreads();
        // build z tile (zero outside image -> conv zero padding)
        for (int i = tid; i < 68 * 68; i += 256) {
            int zy = i / 68, zx = i % 68;
            int jx = jxs[zx], jy = jys[zy];
            float v = 0.f;
            if ((jx | jy) >= 0) {
                float fx = fxs[zx], fy = fys[zy];
                const float* p0 = ds + jy * 26 + jx;
                float a = p0[0], bb = p0[1], cc2 = p0[26], dd = p0[27];
                float top = a + fx * (bb - a);
                float bot = cc2 + fx * (dd - cc2);
                v = top + fy * (bot - top);
            }
            zs[zy * ZST + zx] = v;
        }
        __syncthreads();
        // 5x5 conv, 4x4 register block
        float tacc[16];
#pragma unroll
        for (int i = 0; i < 16; i++) tacc[i] = 0.f;
        int bx = 4 * ttx, by = 4 * tty;
#pragma unroll
        for (int r = 0; r < 8; r++) {
            float4 za = *(const float4*)&zs[(by + r) * ZST + bx];
            float4 zb = *(const float4*)&zs[(by + r) * ZST + bx + 4];
            float zr[8] = {za.x, za.y, za.z, za.w, zb.x, zb.y, zb.z, zb.w};
#pragma unroll
            for (int oy = 0; oy < 4; oy++) {
                int dy = r - oy;
                if (dy < 0 || dy > 4) continue;
#pragma unroll
                for (int dx = 0; dx < 5; dx++) {
                    float w = kk[dy * 5 + dx];
#pragma unroll
                    for (int ox = 0; ox < 4; ox++)
                        tacc[oy * 4 + ox] = fmaf(w, zr[ox + dx], tacc[oy * 4 + ox]);
                }
            }
        }
#pragma unroll
        for (int i = 0; i < 16; i++) {
            float v = fmaf(tacc[i], A, Bc);
            sacc[i] += leaky_(v);
        }
        __syncthreads();   // before next level overwrites smem
    }
    float* out = g_score + (size_t)plane * 512 * 512;
#pragma unroll
    for (int oy = 0; oy < 4; oy++) {
        int gy = ty0 + 4 * tty + oy;
        float4 v = make_float4(sacc[oy * 4 + 0], sacc[oy * 4 + 1], sacc[oy * 4 + 2], sacc[oy * 4 + 3]);
        *(float4*)&out[(size_t)gy * 512 + tx0 + 4 * ttx] = v;
    }
}

// ---------------- K5: ft round = affine(BN + shared 1x1) + 11x11 box emphase ----------------
// dir=0: g_score -> ext ; dir=1: ext -> g_score
#define SINST 139
#define RSST 129
__global__ __launch_bounds__(256) void k_ft(
    int dir, float* ext,
    const float* __restrict__ ft_gamma, const float* __restrict__ ft_beta,
    const float* __restrict__ ft_mean, const float* __restrict__ ft_var,
    const float* __restrict__ ft_k, const float* __restrict__ ft_b,
    const float* __restrict__ emph_w) {
    __shared__ float sin_[42 * SINST];
    __shared__ float rsum[42 * RSST];
    int plane = blockIdx.z;
    int c = plane & 63;
    int x0 = blockIdx.x * 128, y0 = blockIdx.y * 32;
    int tid = threadIdx.x;
    float scale = ft_gamma[c] * rsqrtf(ft_var[c] + 1e-5f);
    float A = ft_k[0] * scale;
    float B = (ft_beta[c] - ft_mean[c] * scale) * ft_k[0] + ft_b[0];
    float w = emph_w[c];
    const float* in = dir ? ext : g_score;
    float* outp = dir ? g_score : ext;
    const float* ip = in + (size_t)plane * 512 * 512;

    for (int i = tid; i < 42 * 138; i += 256) {
        int r = i / 138, cc = i % 138;
        int gy = y0 - 5 + r, gx = x0 - 5 + cc;
        float v = 0.f;
        if (gy >= 0 && gy < 512 && gx >= 0 && gx < 512) v = ip[(size_t)gy * 512 + gx];
        sin_[r * SINST + cc] = v;
    }
    __syncthreads();
    // stage 1: horizontal 11-sums (sliding)
    if (tid < 168) {
        int row = tid % 42, chunk = tid / 42;
        int cs = chunk * 32;
        const float* rp = sin_ + row * SINST;
        float s = 0.f;
#pragma unroll
        for (int i = 0; i < 11; i++) s += rp[cs + i];
        float* rs = rsum + row * RSST;
        rs[cs] = s;
        for (int ci = 1; ci < 32; ci++) {
            s += rp[cs + ci + 10] - rp[cs + ci - 1];
            rs[cs + ci] = s;
        }
    }
    __syncthreads();
    // stage 2: vertical 11-sums (rolling) + emphase + write
    {
        int col = tid & 127, rc = tid >> 7;
        int r0 = rc * 16;
        float vs = 0.f;
#pragma unroll
        for (int r = 0; r < 11; r++) vs += rsum[(r0 + r) * RSST + col];
        float* op = outp + (size_t)plane * 512 * 512;
        int gx = x0 + col;
        int cw = min(gx + 5, 511) - max(gx - 5, 0) + 1;
        for (int ro = 0; ro < 16; ro++) {
            int gy = y0 + r0 + ro;
            int ch2 = min(gy + 5, 511) - max(gy - 5, 0) + 1;
            float cnt = (float)(ch2 * cw);
            float sc = sin_[(5 + r0 + ro) * SINST + 5 + col];
            float s2 = fmaf(sc, A, B);
            float avg = fmaf(vs, A, B * cnt) * (1.0f / 121.0f);
            op[(size_t)gy * 512 + gx] = s2 + w * (s2 - avg);
            if (ro < 15) vs += rsum[(r0 + ro + 11) * RSST + col] - rsum[(r0 + ro) * RSST + col];
        }
    }
}

// ---------------- launch ----------------
extern "C" void kernel_launch(void* const* d_in, const int* in_sizes, int n_in,
                              void* d_out, int out_size) {
    const float* x        = (const float*)d_in[0];
    const float* w1       = (const float*)d_in[1];
    const float* b1       = (const float*)d_in[2];
    const float* w2       = (const float*)d_in[3];
    const float* b2       = (const float*)d_in[4];
    const float* down_k   = (const float*)d_in[5];
    const float* down_b   = (const float*)d_in[6];
    const float* ft_gamma = (const float*)d_in[7];
    const float* ft_beta  = (const float*)d_in[8];
    const float* ft_mean  = (const float*)d_in[9];
    const float* ft_var   = (const float*)d_in[10];
    const float* ft_k     = (const float*)d_in[11];
    const float* ft_b     = (const float*)d_in[12];
    const float* emph_w   = (const float*)d_in[13];
    const float* interp_k = (const float*)d_in[14];
    const float* interp_b = (const float*)d_in[15];
    const float* i_gamma  = (const float*)d_in[16];
    const float* i_beta   = (const float*)d_in[17];
    const float* i_mean   = (const float*)d_in[18];
    const float* i_var    = (const float*)d_in[19];
    float* out = (float*)d_out;

    k_bins<<<1024, 256>>>(x);
    k_mode<<<(6 * 504 * 18 + 127) / 128, 128>>>();
    k_d1<<<dim3(6, 21, 2), dim3(32, 8)>>>(w1, b1, w2, b2, down_k, down_b);
    k_down<<<(128 * 56 * 56 + 255) / 256, 256>>>(1, down_k, down_b);
    k_down<<<(128 * 19 * 19 + 255) / 256, 256>>>(2, down_k, down_b);
    k_down<<<(128 * 7 * 7 + 255) / 256, 256>>>(3, down_k, down_b);
    k_down<<<(128 * 3 * 3 + 255) / 256, 256>>>(4, down_k, down_b);
    k_interp<<<dim3(8, 8, 128), 256>>>(interp_k, interp_b, i_gamma, i_beta, i_mean, i_var);
    dim3 fg(4, 16, 128);
    k_ft<<<fg, 256>>>(0, out, ft_gamma, ft_beta, ft_mean, ft_var, ft_k, ft_b, emph_w); // score->out
    k_ft<<<fg, 256>>>(1, out, ft_gamma, ft_beta, ft_mean, ft_var, ft_k, ft_b, emph_w); // out->score
    k_ft<<<fg, 256>>>(0, out, ft_gamma, ft_beta, ft_mean, ft_var, ft_k, ft_b, emph_w); // score->out
}